// round 6
// baseline (speedup 1.0000x reference)
#include <cuda_runtime.h>

// VariantCoeLinear1d: 1D Rusanov FV solver, 128 rows x 2048 pts x 256 steps.
// One CTA per row (128 CTAs, single wave). 256 threads x 8 register points.
//
// R6: triple (u,f,|f'|) float4 halo exchange published PRE-barrier (right
// after the owned poly block, which already computes the boundary f/a), with
// interior interfaces+updates also pre-barrier. Post-barrier tail is just
// 2x LDS.128 -> 2 edge interfaces -> 2 edge updates -> BC -> STG.
// Halo poly recompute deleted (-10 f32x2 ops/thread/step). Step loop
// unrolled 2x so the u<-un register copies vanish via renaming.

#define BATCH 128
#define NPTS  2048
#define STEPS 256
#define TPB   256
#define PPT   8   // TPB*PPT == NPTS

typedef unsigned long long u64;

static __device__ __forceinline__ u64 pk(float lo, float hi) {
    u64 r; asm("mov.b64 %0,{%1,%2};" : "=l"(r) : "f"(lo), "f"(hi)); return r;
}
static __device__ __forceinline__ void upk(float& lo, float& hi, u64 v) {
    asm("mov.b64 {%0,%1},%2;" : "=f"(lo), "=f"(hi) : "l"(v));
}
static __device__ __forceinline__ u64 f2fma(u64 a, u64 b, u64 c) {
    u64 d; asm("fma.rn.f32x2 %0,%1,%2,%3;" : "=l"(d) : "l"(a), "l"(b), "l"(c)); return d;
}
static __device__ __forceinline__ u64 f2mul(u64 a, u64 b) {
    u64 d; asm("mul.rn.f32x2 %0,%1,%2;" : "=l"(d) : "l"(a), "l"(b)); return d;
}

// fh = (f_l + f_r) - max(a_l,a_r) * (u_r - u_l)   (0.5 folded into HL)
static __device__ __forceinline__ float iface(float ul, float fl, float al,
                                              float ur, float fr, float ar) {
    float am = fmaxf(al, ar);
    return fmaf(-am, ur - ul, fl + fr);
}

// Horner pack: f and |f'| for two points, 10 f32x2 ops.
#define POLY_PACK(U, FLO, FHI, ALO, AHI)                                   \
    do {                                                                   \
        u64 _u2 = f2mul(U, U);                                             \
        u64 _t  = f2fma(CB6, _u2, CB4);                                    \
        _t      = f2fma(_t, U, CB3);                                       \
        _t      = f2fma(_t, U, CB2);                                       \
        _t      = f2fma(_t, U, CB1);                                       \
        u64 _F  = f2mul(_t, U);                                            \
        u64 _s  = f2fma(CA5, _u2, CA3);                                    \
        _s      = f2fma(_s, U, CA2);                                       \
        _s      = f2fma(_s, U, CA1);                                       \
        _s      = f2fma(_s, U, CA0);                                       \
        u64 _A  = _s & ABSM;                                               \
        upk(FLO, FHI, _F);                                                 \
        upk(ALO, AHI, _A);                                                 \
    } while (0)

__global__ void __launch_bounds__(TPB, 1)
vcl_kernel(const float* __restrict__ init, float* __restrict__ out)
{
    // double-buffered boundary triples {u, f, a, pad}
    __shared__ float4 sL[2][TPB];   // thread t's FIRST point
    __shared__ float4 sR[2][TPB];   // thread t's LAST point

    const int row  = blockIdx.x;
    const int tid  = threadIdx.x;
    const int base = tid * PPT;
    const int tl   = (tid > 0) ? tid - 1 : 0;              // edge dummies:
    const int tr   = (tid < TPB - 1) ? tid + 1 : TPB - 1;  // overwritten by BC
    const float HL = 0.5f * (float)(0.002 / (10.0 / 2048.0));  // 0.5*dt/dx

    const double c = 0.1 / 12.0;   // beta/12
    const u64 CB1 = pk(1.5f, 1.5f);
    const u64 CB2 = pk((float)(0.75 * c),        (float)(0.75 * c));
    const u64 CB3 = pk((float)(-0.5 - 2.0 * c),  (float)(-0.5 - 2.0 * c));
    const u64 CB4 = pk((float)(1.5 * c),         (float)(1.5 * c));
    const u64 CB6 = pk((float)(-0.25 * c),       (float)(-0.25 * c));
    const u64 CA0 = pk(1.5f, 1.5f);
    const u64 CA1 = pk((float)(1.5 * c),         (float)(1.5 * c));
    const u64 CA2 = pk((float)(-1.5 - 6.0 * c),  (float)(-1.5 - 6.0 * c));
    const u64 CA3 = pk((float)(6.0 * c),         (float)(6.0 * c));
    const u64 CA5 = pk((float)(-1.5 * c),        (float)(-1.5 * c));
    const u64 ABSM = 0x7fffffff7fffffffULL;

    float u[PPT];
    {
        const float4* ip = reinterpret_cast<const float4*>(init + (size_t)row * NPTS + base);
        float4 a0 = ip[0], a1 = ip[1];
        u[0] = a0.x; u[1] = a0.y; u[2] = a0.z; u[3] = a0.w;
        u[4] = a1.x; u[5] = a1.y; u[6] = a1.z; u[7] = a1.w;
        float4* o0 = reinterpret_cast<float4*>(out + (size_t)row * NPTS + base);
        __stcs(o0, a0);
        __stcs(o0 + 1, a1);
    }

    float4* op = reinterpret_cast<float4*>(out + ((size_t)BATCH + row) * NPTS + base);
    const size_t ostride = (size_t)BATCH * NPTS / 4;

    #pragma unroll 2
    for (int s = 1; s < STEPS; ++s) {
        const int b = s & 1;

        // ======== pre-barrier: poly, publish boundary triples, interior ====
        float f[PPT], a[PPT];
        #pragma unroll
        for (int i = 0; i < PPT / 2; ++i) {
            u64 U = pk(u[2 * i], u[2 * i + 1]);
            POLY_PACK(U, f[2 * i], f[2 * i + 1], a[2 * i], a[2 * i + 1]);
        }

        // publish own boundary triples (current step's values)
        sL[b][tid] = make_float4(u[0],       f[0],       a[0],       0.0f);
        sR[b][tid] = make_float4(u[PPT - 1], f[PPT - 1], a[PPT - 1], 0.0f);

        float fh[PPT + 1];
        #pragma unroll
        for (int i = 1; i < PPT; ++i)
            fh[i] = iface(u[i - 1], f[i - 1], a[i - 1], u[i], f[i], a[i]);

        float un[PPT];
        #pragma unroll
        for (int k = 1; k < PPT - 1; ++k)
            un[k] = fmaf(-HL, fh[k + 1] - fh[k], u[k]);

        // ======== barrier (defer-blocking: stalls at the LDS below) ========
        __syncthreads();

        float4 nl = sR[b][tl];   // neighbor-left  (u,f,a)
        float4 nr = sL[b][tr];   // neighbor-right (u,f,a)

        float fh0 = iface(nl.x, nl.y, nl.z, u[0], f[0], a[0]);
        float fhN = iface(u[PPT - 1], f[PPT - 1], a[PPT - 1], nr.x, nr.y, nr.z);
        un[0]       = fmaf(-HL, fh[1] - fh0, u[0]);
        un[PPT - 1] = fmaf(-HL, fhN - fh[PPT - 1], u[PPT - 1]);

        if (tid == 0)       un[0]       = un[1];
        if (tid == TPB - 1) un[PPT - 1] = un[PPT - 2];

        // stream frame (write-only; evict-first)
        __stcs(op,     make_float4(un[0], un[1], un[2], un[3]));
        __stcs(op + 1, make_float4(un[4], un[5], un[6], un[7]));
        op += ostride;

        #pragma unroll
        for (int k = 0; k < PPT; ++k) u[k] = un[k];
    }
}

extern "C" void kernel_launch(void* const* d_in, const int* in_sizes, int n_in,
                              void* d_out, int out_size) {
    const float* init = (const float*)d_in[0];   // [128, 2048] fp32
    // d_in[1] = stepnum (int32) — fixed at 256 by the problem spec
    float* out = (float*)d_out;                  // [256, 128, 2048] fp32
    vcl_kernel<<<BATCH, TPB>>>(init, out);
}

// round 7
// speedup vs baseline: 1.2306x; 1.2306x over previous
#include <cuda_runtime.h>

// VariantCoeLinear1d: 1D Rusanov FV solver, 128 rows x 2048 pts x 256 steps.
// One CTA per row (128 CTAs, single wave).
//
// R7 = R5 structure (Horner f32x2 packs, u-only double-buffered scalar SMEM
// halos published at end-of-step, one barrier at top-of-step, interior math
// hoisted pre-barrier) at DOUBLE OCCUPANCY: 512 threads x 4 points each
// (4 warps/SMSP, occ 25%) to fill the latency bubbles that capped R4-R6
// (issue% stuck at 44-63% with 2 warps/SMSP).

#define BATCH 128
#define NPTS  2048
#define STEPS 256
#define TPB   512
#define PPT   4   // TPB*PPT == NPTS

typedef unsigned long long u64;

static __device__ __forceinline__ u64 pk(float lo, float hi) {
    u64 r; asm("mov.b64 %0,{%1,%2};" : "=l"(r) : "f"(lo), "f"(hi)); return r;
}
static __device__ __forceinline__ void upk(float& lo, float& hi, u64 v) {
    asm("mov.b64 {%0,%1},%2;" : "=f"(lo), "=f"(hi) : "l"(v));
}
static __device__ __forceinline__ u64 f2fma(u64 a, u64 b, u64 c) {
    u64 d; asm("fma.rn.f32x2 %0,%1,%2,%3;" : "=l"(d) : "l"(a), "l"(b), "l"(c)); return d;
}
static __device__ __forceinline__ u64 f2mul(u64 a, u64 b) {
    u64 d; asm("mul.rn.f32x2 %0,%1,%2;" : "=l"(d) : "l"(a), "l"(b)); return d;
}

// fh = (f_l + f_r) - max(a_l,a_r) * (u_r - u_l)   (0.5 folded into HL)
static __device__ __forceinline__ float iface(float ul, float fl, float al,
                                              float ur, float fr, float ar) {
    float am = fmaxf(al, ar);
    return fmaf(-am, ur - ul, fl + fr);
}

// Horner pack: f and |f'| for two points, 10 f32x2 ops.
#define POLY_PACK(U, FLO, FHI, ALO, AHI)                                   \
    do {                                                                   \
        u64 _u2 = f2mul(U, U);                                             \
        u64 _t  = f2fma(CB6, _u2, CB4);                                    \
        _t      = f2fma(_t, U, CB3);                                       \
        _t      = f2fma(_t, U, CB2);                                       \
        _t      = f2fma(_t, U, CB1);                                       \
        u64 _F  = f2mul(_t, U);                                            \
        u64 _s  = f2fma(CA5, _u2, CA3);                                    \
        _s      = f2fma(_s, U, CA2);                                       \
        _s      = f2fma(_s, U, CA1);                                       \
        _s      = f2fma(_s, U, CA0);                                       \
        u64 _A  = _s & ABSM;                                               \
        upk(FLO, FHI, _F);                                                 \
        upk(ALO, AHI, _A);                                                 \
    } while (0)

__global__ void __launch_bounds__(TPB, 1)
vcl_kernel(const float* __restrict__ init, float* __restrict__ out)
{
    __shared__ float sL[2][TPB];   // thread t's FIRST point
    __shared__ float sR[2][TPB];   // thread t's LAST point

    const int row  = blockIdx.x;
    const int tid  = threadIdx.x;
    const int base = tid * PPT;
    const int tl   = (tid > 0) ? tid - 1 : 0;              // edge dummies:
    const int tr   = (tid < TPB - 1) ? tid + 1 : TPB - 1;  // overwritten by BC
    const float HL = 0.5f * (float)(0.002 / (10.0 / 2048.0));  // 0.5*dt/dx

    const double c = 0.1 / 12.0;   // beta/12
    const u64 CB1 = pk(1.5f, 1.5f);
    const u64 CB2 = pk((float)(0.75 * c),        (float)(0.75 * c));
    const u64 CB3 = pk((float)(-0.5 - 2.0 * c),  (float)(-0.5 - 2.0 * c));
    const u64 CB4 = pk((float)(1.5 * c),         (float)(1.5 * c));
    const u64 CB6 = pk((float)(-0.25 * c),       (float)(-0.25 * c));
    const u64 CA0 = pk(1.5f, 1.5f);
    const u64 CA1 = pk((float)(1.5 * c),         (float)(1.5 * c));
    const u64 CA2 = pk((float)(-1.5 - 6.0 * c),  (float)(-1.5 - 6.0 * c));
    const u64 CA3 = pk((float)(6.0 * c),         (float)(6.0 * c));
    const u64 CA5 = pk((float)(-1.5 * c),        (float)(-1.5 * c));
    const u64 ABSM = 0x7fffffff7fffffffULL;

    float u[PPT];
    {
        const float4* ip = reinterpret_cast<const float4*>(init + (size_t)row * NPTS + base);
        float4 a0 = ip[0];
        u[0] = a0.x; u[1] = a0.y; u[2] = a0.z; u[3] = a0.w;
        float4* o0 = reinterpret_cast<float4*>(out + (size_t)row * NPTS + base);
        __stcs(o0, a0);
    }
    sL[0][tid] = u[0];
    sR[0][tid] = u[PPT - 1];

    float4* op = reinterpret_cast<float4*>(out + ((size_t)BATCH + row) * NPTS + base);
    const size_t ostride = (size_t)BATCH * NPTS / 4;

    int p = 0;
    #pragma unroll 1
    for (int s = 1; s < STEPS; ++s) {
        // ======== pre-barrier: owned polys + interior interfaces/updates ====
        float f[PPT], a[PPT];
        #pragma unroll
        for (int i = 0; i < PPT / 2; ++i) {
            u64 U = pk(u[2 * i], u[2 * i + 1]);
            POLY_PACK(U, f[2 * i], f[2 * i + 1], a[2 * i], a[2 * i + 1]);
        }

        float fh[PPT + 1];
        #pragma unroll
        for (int i = 1; i < PPT; ++i)
            fh[i] = iface(u[i - 1], f[i - 1], a[i - 1], u[i], f[i], a[i]);

        float un[PPT];
        #pragma unroll
        for (int k = 1; k < PPT - 1; ++k)
            un[k] = fmaf(-HL, fh[k + 1] - fh[k], u[k]);

        // ======== barrier separates prev-step publishes from halo reads ====
        __syncthreads();

        float um = sR[p][tl];
        float up = sL[p][tr];

        float fm, frr, am, arr;
        {
            u64 U = pk(um, up);
            POLY_PACK(U, fm, frr, am, arr);
        }

        fh[0]   = iface(um, fm, am, u[0], f[0], a[0]);
        fh[PPT] = iface(u[PPT - 1], f[PPT - 1], a[PPT - 1], up, frr, arr);
        un[0]       = fmaf(-HL, fh[1] - fh[0], u[0]);
        un[PPT - 1] = fmaf(-HL, fh[PPT] - fh[PPT - 1], u[PPT - 1]);

        if (tid == 0)       un[0]       = un[1];
        if (tid == TPB - 1) un[PPT - 1] = un[PPT - 2];

        // publish next-step boundaries (other buffer; next barrier fences)
        const int np = p ^ 1;
        sL[np][tid] = un[0];
        sR[np][tid] = un[PPT - 1];

        // stream frame (write-only; evict-first)
        __stcs(op, make_float4(un[0], un[1], un[2], un[3]));
        op += ostride;

        #pragma unroll
        for (int k = 0; k < PPT; ++k) u[k] = un[k];
        p = np;
    }
}

extern "C" void kernel_launch(void* const* d_in, const int* in_sizes, int n_in,
                              void* d_out, int out_size) {
    const float* init = (const float*)d_in[0];   // [128, 2048] fp32
    // d_in[1] = stepnum (int32) — fixed at 256 by the problem spec
    float* out = (float*)d_out;                  // [256, 128, 2048] fp32
    vcl_kernel<<<BATCH, TPB>>>(init, out);
}